// round 11
// baseline (speedup 1.0000x reference)
#include <cuda_runtime.h>
#include <cstdint>

#define Bq 2
#define Hq 8
#define Sq 2048
#define Dq 64
#define TEMP 8.0f

#define BM 128
#define BN 64
#define NT 512
#define NTILES (Sq / BN)   // 32

// smem word offsets
#define W_Q   0                      // q tf32 [128][68]
#define W_K0  8704                   // k raw f32 [64][68] natural [t][d], buf 0
#define W_K1  13056                  // buf 1
#define W_VR0 17408                  // v raw f32 [64][68] natural [t][d], buf 0
#define W_VR1 21760                  // buf 1
#define W_E   26112                  // e tf32-rounded f32 [128][76] ([row][t])
#define W_RS  35840                  // rowsum [4][128] floats
#define SMEM_WORDS 36352
#define SMEM_BYTES (SMEM_WORDS * 4)  // 145408 B

#define KVS 68     // K / Vraw row stride (words)
#define ES  76     // E row stride (words): AV A-loads conflict-free

// masked-cov scratch: covm = mask ? cov : -3e4   (33.5 MB)
__device__ float g_covm[(size_t)Bq * Sq * Sq];

static __device__ __forceinline__ uint32_t f2tf32(float f) {
    uint32_t r;
    asm("cvt.rna.tf32.f32 %0, %1;" : "=r"(r) : "f"(f));
    return r;
}
// exp(x) on fma/alu pipes only (no MUFU). Caller clamps x >= -60.
static __device__ __forceinline__ float fexp(float x) {
    const float L2E = 1.4426950408889634f;
    float t = fmaf(x, L2E, 12582912.0f);          // 1.5*2^23: rounds to int
    int   in = __float_as_int(t);
    float n  = t - 12582912.0f;
    float z  = fmaf(x, L2E, -n);                  // frac in [-0.5, 0.5]
    float w  = z * 0.6931471805599453f;
    float p  = fmaf(w, 8.3333333e-3f, 4.1666667e-2f);
    p = fmaf(p, w, 0.16666667f);
    p = fmaf(p, w, 0.5f);
    p = fmaf(p, w, 1.0f);
    p = fmaf(p, w, 1.0f);
    return __int_as_float(__float_as_int(p) + (in << 23));
}
static __device__ __forceinline__ void mma_tf32(float* d, const uint32_t* a,
                                                const uint32_t* b) {
    asm volatile(
        "mma.sync.aligned.m16n8k8.row.col.f32.tf32.tf32.f32 "
        "{%0,%1,%2,%3}, {%4,%5,%6,%7}, {%8,%9}, {%0,%1,%2,%3};"
        : "+f"(d[0]), "+f"(d[1]), "+f"(d[2]), "+f"(d[3])
        : "r"(a[0]), "r"(a[1]), "r"(a[2]), "r"(a[3]), "r"(b[0]), "r"(b[1]));
}
static __device__ __forceinline__ void cp16(uint32_t dst, const void* src) {
    asm volatile("cp.async.cg.shared.global [%0], [%1], 16;"
                 :: "r"(dst), "l"(src) : "memory");
}

// Pre-kernel: fold mask into cov (one streaming pass, high occupancy)
__global__ __launch_bounds__(256, 8)
void covmask_kernel(const float* __restrict__ cov, const int* __restrict__ mask)
{
    size_t i = ((size_t)blockIdx.x * 256 + threadIdx.x) * 4;
    float4 c = *(const float4*)(cov + i);
    int4   m = *(const int4*)(mask + i);
    float4 o;
    o.x = m.x ? c.x : -30000.0f;
    o.y = m.y ? c.y : -30000.0f;
    o.z = m.z ? c.z : -30000.0f;
    o.w = m.w ? c.w : -30000.0f;
    *(float4*)(g_covm + i) = o;
}

__global__ __launch_bounds__(NT, 1)
void attn_mma_kernel(const float* __restrict__ q,
                     const float* __restrict__ k,
                     const float* __restrict__ v,
                     const float* __restrict__ lambda_w,
                     float* __restrict__ out,      // [B,H,S,D]
                     float* __restrict__ attn)     // [B,H,S,S]
{
    extern __shared__ uint32_t sw[];
    const uint32_t sbase = (uint32_t)__cvta_generic_to_shared(sw);
    uint32_t* QW = sw + W_Q;
    uint32_t* EW = sw + W_E;
    float*    rs = (float*)(sw + W_RS);

    const int h     = blockIdx.x;   // innermost -> heads share covm in L2
    const int mpair = blockIdx.y;   // 2 mtiles per CTA
    const int b     = blockIdx.z;
    const int bh    = b * Hq + h;
    const int tid   = threadIdx.x;
    const int wid   = tid >> 5;
    const int lane  = tid & 31;
    const int lg    = lane >> 2;    // group 0..7
    const int lt    = lane & 3;     // 0..3

    const int warp_m = wid & 3;     // row group (32 rows)
    const int warp_n = wid >> 2;    // 0..3: 16-col / 16-d slice
    const int rm = warp_m * 32;
    const int cn = warp_n * 16;
    const int dn = warp_n * 16;

    const float lam  = lambda_w[h];
    const float wcov = lam / (lam + 1.0f);
    const float sqk  = 1.0f / ((lam + 1.0f) * TEMP);

    const float* kg = k + (size_t)bh * Sq * Dq;
    const float* vg = v + (size_t)bh * Sq * Dq;

    for (int m = 0; m < 2; m++) {
        const int mtile = mpair * 2 + m;
        const float* qg    = q + ((size_t)bh * Sq + (size_t)mtile * BM) * Dq;
        const float* covg  = g_covm + ((size_t)b * Sq + (size_t)mtile * BM) * Sq;
        float*       attng = attn + ((size_t)bh * Sq + (size_t)mtile * BM) * Sq;
        float*       outg  = out  + ((size_t)bh * Sq + (size_t)mtile * BM) * Dq;

        __syncthreads();   // previous mtile fully done (QW/E/VR free)

        // ---- prefetch tile 0 (K + Vraw) ----
        {
#pragma unroll
            for (int it = 0; it < 2; it++) {
                int idx = tid + it * NT;   // 1024 16B segs each
                int t   = idx >> 4;
                int seg = idx & 15;
                cp16(sbase + (uint32_t)(W_K0  + t * KVS + seg * 4) * 4,
                     kg + (size_t)t * Dq + seg * 4);
                cp16(sbase + (uint32_t)(W_VR0 + t * KVS + seg * 4) * 4,
                     vg + (size_t)t * Dq + seg * 4);
            }
            asm volatile("cp.async.commit_group;" ::: "memory");
        }

        // ---- fill q smem (tf32) ----
#pragma unroll
        for (int it = 0; it < 4; it++) {
            int idx = tid + it * NT;        // 2048 float4
            int r  = idx >> 4;
            int c4 = (idx & 15) << 2;
            float4 f = *(const float4*)&qg[r * Dq + c4];
            uint4 o;
            o.x = f2tf32(f.x); o.y = f2tf32(f.y);
            o.z = f2tf32(f.z); o.w = f2tf32(f.w);
            *(uint4*)&QW[r * 68 + c4] = o;
        }

        float oacc[2][2][4];
#pragma unroll
        for (int mi = 0; mi < 2; mi++)
#pragma unroll
            for (int nf = 0; nf < 2; nf++)
#pragma unroll
                for (int c = 0; c < 4; c++) oacc[mi][nf][c] = 0.0f;
        float rowsum[4] = {0.0f, 0.0f, 0.0f, 0.0f};

        for (int nt = 0; nt < NTILES; nt++) {
            const int buf = nt & 1;
            const int kof = buf ? W_K1 : W_K0;
            const int vof = buf ? W_VR1 : W_VR0;
            const int t0  = nt * BN;

            // wait for current tile's data; barrier also proves AV(nt-1)
            // finished reading the other buffer before we overwrite it.
            asm volatile("cp.async.wait_group 0;" ::: "memory");
            __syncthreads();

            // ---- prefetch next tile (safe now) ----
            if (nt + 1 < NTILES) {
                const int kofn = buf ? W_K0 : W_K1;
                const int vofn = buf ? W_VR0 : W_VR1;
                const float* kn = kg + (size_t)(t0 + BN) * Dq;
                const float* vn = vg + (size_t)(t0 + BN) * Dq;
#pragma unroll
                for (int it = 0; it < 2; it++) {
                    int idx = tid + it * NT;
                    int t   = idx >> 4;
                    int seg = idx & 15;
                    cp16(sbase + (uint32_t)(kofn + t * KVS + seg * 4) * 4,
                         kn + (size_t)t * Dq + seg * 4);
                    cp16(sbase + (uint32_t)(vofn + t * KVS + seg * 4) * 4,
                         vn + (size_t)t * Dq + seg * 4);
                }
                asm volatile("cp.async.commit_group;" ::: "memory");
            }

            // ---- cov prefetch (hidden behind QK MMA) ----
            float2 cv[2][2][2];
#pragma unroll
            for (int mi = 0; mi < 2; mi++)
#pragma unroll
                for (int rh = 0; rh < 2; rh++) {
                    const int r = rm + mi * 16 + lg + rh * 8;
#pragma unroll
                    for (int ni = 0; ni < 2; ni++)
                        cv[mi][rh][ni] = *(const float2*)
                            (covg + (size_t)r * Sq + t0 + cn + ni * 8 + 2 * lt);
                }

            // ---- scores: warp tile 32 rows x 16 cols, tf32 mma ----
            const uint32_t* KB = sw + kof;   // natural [t][d], raw f32 as tf32
            float acc[2][2][4];
#pragma unroll
            for (int mi = 0; mi < 2; mi++)
#pragma unroll
                for (int ni = 0; ni < 2; ni++)
#pragma unroll
                    for (int c = 0; c < 4; c++) acc[mi][ni][c] = 0.0f;

#pragma unroll
            for (int ks = 0; ks < 8; ks++) {
                const int kd = ks * 8;
                uint32_t a[2][4], bb[2][2];
#pragma unroll
                for (int mi = 0; mi < 2; mi++) {
                    const uint32_t* q0 = QW + (rm + mi * 16 + lg) * 68 + kd + lt;
                    a[mi][0] = q0[0];
                    a[mi][1] = q0[8 * 68];
                    a[mi][2] = q0[4];
                    a[mi][3] = q0[8 * 68 + 4];
                }
#pragma unroll
                for (int ni = 0; ni < 2; ni++) {
                    const uint32_t* kp = KB + (cn + ni * 8 + lg) * KVS + kd + lt;
                    bb[ni][0] = kp[0];
                    bb[ni][1] = kp[4];
                }
#pragma unroll
                for (int mi = 0; mi < 2; mi++)
#pragma unroll
                    for (int ni = 0; ni < 2; ni++)
                        mma_tf32(acc[mi][ni], a[mi], bb[ni]);
            }

            // ---- epilogue: blend, exp, attn store, e (tf32-rounded) to E ----
#pragma unroll
            for (int mi = 0; mi < 2; mi++) {
#pragma unroll
                for (int rh = 0; rh < 2; rh++) {
                    const int r = rm + mi * 16 + lg + rh * 8;
                    float* ar = attng + (size_t)r * Sq + t0;
                    float rsacc = 0.0f;
#pragma unroll
                    for (int ni = 0; ni < 2; ni++) {
                        const int c = cn + ni * 8 + 2 * lt;
                        float s0 = acc[mi][ni][rh * 2 + 0];
                        float s1 = acc[mi][ni][rh * 2 + 1];
                        float l0 = fmaxf(fmaf(sqk, s0, wcov * cv[mi][rh][ni].x), -60.0f);
                        float l1 = fmaxf(fmaf(sqk, s1, wcov * cv[mi][rh][ni].y), -60.0f);
                        float e0 = fexp(l0);
                        float e1 = fexp(l1);
                        rsacc += e0 + e1;
                        *(float2*)(ar + c) = make_float2(e0, e1);
                        uint2 er;
                        er.x = f2tf32(e0);
                        er.y = f2tf32(e1);
                        *(uint2*)&EW[r * ES + c] = er;
                    }
                    rowsum[mi * 2 + rh] += rsacc;
                }
            }
            __syncthreads();

            // ---- AV: warp tile 32 rows x 16 d, tf32 k8, k=64 in 8 steps ----
            const float* VRf = (const float*)(sw + vof);  // natural [t][d]
#pragma unroll
            for (int ks = 0; ks < 8; ks++) {
                const int tb = ks * 8;
                uint32_t a[2][4], bb[2][2];
#pragma unroll
                for (int mi = 0; mi < 2; mi++) {
                    const uint32_t* e0 = EW + (rm + mi * 16 + lg) * ES + tb + lt;
                    a[mi][0] = e0[0];
                    a[mi][1] = e0[8 * ES];
                    a[mi][2] = e0[4];
                    a[mi][3] = e0[8 * ES + 4];
                }
#pragma unroll
                for (int nf = 0; nf < 2; nf++) {
                    const float* vp = VRf + (tb + lt) * KVS + dn + nf * 8 + lg;
                    bb[nf][0] = f2tf32(vp[0]);
                    bb[nf][1] = f2tf32(vp[4 * KVS]);
                }
#pragma unroll
                for (int mi = 0; mi < 2; mi++)
#pragma unroll
                    for (int nf = 0; nf < 2; nf++)
                        mma_tf32(oacc[mi][nf], a[mi], bb[nf]);
            }
        }

        // ---- rowsum: reduce over lane&3, store partials ----
#pragma unroll
        for (int i = 0; i < 4; i++) {
            rowsum[i] += __shfl_xor_sync(0xffffffffu, rowsum[i], 1);
            rowsum[i] += __shfl_xor_sync(0xffffffffu, rowsum[i], 2);
        }
        __syncthreads();   // E/VR reads done before rs reuse is irrelevant; order rs writes
        if (lt == 0) {
#pragma unroll
            for (int mi = 0; mi < 2; mi++)
#pragma unroll
                for (int rh = 0; rh < 2; rh++)
                    rs[warp_n * 128 + rm + mi * 16 + lg + rh * 8] = rowsum[mi * 2 + rh];
        }
        __syncthreads();

        // ---- write normalized output ----
#pragma unroll
        for (int mi = 0; mi < 2; mi++) {
#pragma unroll
            for (int rh = 0; rh < 2; rh++) {
                const int r = rm + mi * 16 + lg + rh * 8;
                const float iv = 1.0f /
                    (rs[r] + rs[128 + r] + rs[256 + r] + rs[384 + r]);
#pragma unroll
                for (int nf = 0; nf < 2; nf++) {
                    const int d = dn + nf * 8 + 2 * lt;
                    float2 o;
                    o.x = oacc[mi][nf][rh * 2 + 0] * iv;
                    o.y = oacc[mi][nf][rh * 2 + 1] * iv;
                    *(float2*)(outg + (size_t)r * Dq + d) = o;
                }
            }
        }

        // ---- fused normalize tail: scale this mtile's attn slice ----
        {
            const int rlane = tid >> 7;          // 0..3
            const int ci    = tid & 127;         // float4 col
#pragma unroll 2
            for (int rb = 0; rb < 32; rb++) {
                const int r = rb * 4 + rlane;
                const float iv = 1.0f /
                    (rs[r] + rs[128 + r] + rs[256 + r] + rs[384 + r]);
                float4* arow = (float4*)(attng + (size_t)r * Sq);
                float4 x0 = arow[ci];
                float4 x1 = arow[ci + 128];
                float4 x2 = arow[ci + 256];
                float4 x3 = arow[ci + 384];
                x0.x *= iv; x0.y *= iv; x0.z *= iv; x0.w *= iv;
                x1.x *= iv; x1.y *= iv; x1.z *= iv; x1.w *= iv;
                x2.x *= iv; x2.y *= iv; x2.z *= iv; x2.w *= iv;
                x3.x *= iv; x3.y *= iv; x3.z *= iv; x3.w *= iv;
                arow[ci]       = x0;
                arow[ci + 128] = x1;
                arow[ci + 256] = x2;
                arow[ci + 384] = x3;
            }
        }
    }
}

extern "C" void kernel_launch(void* const* d_in, const int* in_sizes, int n_in,
                              void* d_out, int out_size)
{
    const float* q    = (const float*)d_in[0];
    const float* k    = (const float*)d_in[1];
    const float* v    = (const float*)d_in[2];
    const float* cov  = (const float*)d_in[3];
    const float* lam  = (const float*)d_in[4];
    const int*   mask = (const int*)d_in[5];

    float* out  = (float*)d_out;                          // [B,H,S,D]
    float* attn = out + (size_t)Bq * Hq * Sq * Dq;        // [B,H,S,S]

    // pass 0: fold mask into cov (streaming)
    const size_t n4 = (size_t)Bq * Sq * Sq / 4;
    covmask_kernel<<<(unsigned)(n4 / 256), 256>>>(cov, mask);

    cudaFuncSetAttribute(attn_mma_kernel,
                         cudaFuncAttributeMaxDynamicSharedMemorySize, SMEM_BYTES);
    dim3 grid(Hq, Sq / BM / 2, Bq);  // (8, 8, 2) = 128 CTAs, single wave
    attn_mma_kernel<<<grid, NT, SMEM_BYTES>>>(q, k, v, lam, out, attn);
}